// round 3
// baseline (speedup 1.0000x reference)
#include <cuda_runtime.h>

#define NG 1024
#define NFEAT 128
#define NQUAD 32          // 128 floats = 32 float4 per row
#define RG 8              // row-groups per block in the pooling kernel

__device__ int   g_start[NG];
__device__ int   g_cnt[NG];
__device__ float g_inv[NG];

// ---------------------------------------------------------------------------
// K1: segment bounds via binary search on sorted batch (int32). 1024 threads.
// ---------------------------------------------------------------------------
__global__ void seg_bounds_kernel(const int* __restrict__ batch, int n) {
    int g = blockIdx.x * blockDim.x + threadIdx.x;
    if (g >= NG) return;

    // lower_bound(g)
    int lo = 0, hi = n;
    while (lo < hi) {
        int mid = (lo + hi) >> 1;
        if (batch[mid] < g) lo = mid + 1; else hi = mid;
    }
    int lb = lo;

    // lower_bound(g+1)
    hi = n;
    int g1 = g + 1;
    while (lo < hi) {
        int mid = (lo + hi) >> 1;
        if (batch[mid] < g1) lo = mid + 1; else hi = mid;
    }
    int cnt = lo - lb;

    g_start[g] = lb;
    g_cnt[g]   = cnt;
    g_inv[g]   = 1.0f / (float)(cnt > 1 ? cnt : 1);
}

// ---------------------------------------------------------------------------
// K2: per-graph mean pooling. One block per graph, 256 threads.
// Thread (rgrp = tid>>5, quad = tid&31): strides rows by RG, float4 loads.
// Deterministic: fixed per-thread accumulation order + fixed tree reduction.
// ---------------------------------------------------------------------------
__global__ __launch_bounds__(256) void pool_kernel(const float* __restrict__ x,
                                                   float* __restrict__ pooled) {
    int g    = blockIdx.x;
    int tid  = threadIdx.x;
    int quad = tid & (NQUAD - 1);
    int rgrp = tid >> 5;

    int start = g_start[g];
    int n     = g_cnt[g];
    float inv = g_inv[g];

    const float4* __restrict__ x4 = (const float4*)x;

    float4 acc = make_float4(0.f, 0.f, 0.f, 0.f);

    // Unrolled-by-4 main loop: 4 independent outstanding 16B loads per thread.
    int r = rgrp;
    int nmain = n - 3 * RG;  // can take 4 strided rows while r < nmain
    for (; r < nmain; r += 4 * RG) {
        float4 v0 = x4[(size_t)(start + r         ) * NQUAD + quad];
        float4 v1 = x4[(size_t)(start + r + 1 * RG) * NQUAD + quad];
        float4 v2 = x4[(size_t)(start + r + 2 * RG) * NQUAD + quad];
        float4 v3 = x4[(size_t)(start + r + 3 * RG) * NQUAD + quad];
        acc.x += v0.x; acc.y += v0.y; acc.z += v0.z; acc.w += v0.w;
        acc.x += v1.x; acc.y += v1.y; acc.z += v1.z; acc.w += v1.w;
        acc.x += v2.x; acc.y += v2.y; acc.z += v2.z; acc.w += v2.w;
        acc.x += v3.x; acc.y += v3.y; acc.z += v3.z; acc.w += v3.w;
    }
    for (; r < n; r += RG) {
        float4 v = x4[(size_t)(start + r) * NQUAD + quad];
        acc.x += v.x; acc.y += v.y; acc.z += v.z; acc.w += v.w;
    }

    __shared__ float4 smem[RG * NQUAD];
    smem[rgrp * NQUAD + quad] = acc;
    __syncthreads();

    // tree reduce over row-groups: 8 -> 4 -> 2 -> 1
    #pragma unroll
    for (int half = RG / 2; half >= 1; half >>= 1) {
        if (rgrp < half) {
            float4 a = smem[rgrp * NQUAD + quad];
            float4 b = smem[(rgrp + half) * NQUAD + quad];
            a.x += b.x; a.y += b.y; a.z += b.z; a.w += b.w;
            smem[rgrp * NQUAD + quad] = a;
        }
        __syncthreads();
    }

    if (rgrp == 0) {
        float4 s = smem[quad];
        s.x *= inv; s.y *= inv; s.z *= inv; s.w *= inv;
        ((float4*)pooled)[(size_t)g * NQUAD + quad] = s;
    }
}

// ---------------------------------------------------------------------------
// K3: attention_scores[i] = inv[batch[i]]. 4 nodes per thread (int4 read,
// float4 write).
// ---------------------------------------------------------------------------
__global__ __launch_bounds__(256) void attn_kernel(const int* __restrict__ batch,
                                                   float* __restrict__ attn, int n) {
    int i4 = blockIdx.x * blockDim.x + threadIdx.x;   // quad index
    int nquads = n >> 2;
    if (i4 < nquads) {
        int4 b = ((const int4*)batch)[i4];
        float4 o;
        o.x = g_inv[b.x];
        o.y = g_inv[b.y];
        o.z = g_inv[b.z];
        o.w = g_inv[b.w];
        ((float4*)attn)[i4] = o;
    }
    // tail (n not divisible by 4) handled by thread 0
    if (i4 == 0) {
        for (int i = nquads << 2; i < n; i++)
            attn[i] = g_inv[batch[i]];
    }
}

// ---------------------------------------------------------------------------
extern "C" void kernel_launch(void* const* d_in, const int* in_sizes, int n_in,
                              void* d_out, int out_size) {
    const float* x     = (const float*)d_in[0];
    // d_in[1] = edge_index (unused by the reference)
    const int*   batch = (const int*)d_in[2];
    int n = in_sizes[2];               // number of nodes (1,000,000)

    float* pooled = (float*)d_out;                 // [NG, NFEAT]
    float* attn   = (float*)d_out + NG * NFEAT;    // [n]

    seg_bounds_kernel<<<(NG + 255) / 256, 256>>>(batch, n);
    pool_kernel<<<NG, 256>>>(x, pooled);
    int nquads = n >> 2;
    attn_kernel<<<(nquads + 255) / 256, 256>>>(batch, attn, n);
}

// round 4
// speedup vs baseline: 1.0987x; 1.0987x over previous
#include <cuda_runtime.h>

#define NG 1024
#define NFEAT 128
#define NQUAD 32          // 128 floats = 32 float4 per row
#define RG 8              // row-groups per block in the pooling kernel

// g_start[g] = index of first node of graph g; g_start[NG] = n.
__device__ int g_start[NG + 1];

// ---------------------------------------------------------------------------
// K1: boundary detection on sorted batch. One thread per node, streaming.
// Writes happen only at segment boundaries (plus empty-graph fill-in).
// ---------------------------------------------------------------------------
__global__ __launch_bounds__(256) void bounds_kernel(const int* __restrict__ batch, int n) {
    int i = blockIdx.x * blockDim.x + threadIdx.x;
    if (i >= n) return;

    int cur  = batch[i];
    int prev = (i == 0) ? -1 : batch[i - 1];

    // all graphs in (prev, cur] start at i (covers empty graphs)
    for (int g = prev + 1; g <= cur; g++)
        g_start[g] = i;

    if (i == n - 1) {
        for (int g = cur + 1; g <= NG; g++)
            g_start[g] = n;
    }
}

// ---------------------------------------------------------------------------
// K2: per-graph mean pooling. One block per graph, 256 threads.
// Thread (rgrp = tid>>5, quad = tid&31): strides rows by RG, float4 loads.
// Deterministic: fixed per-thread accumulation order + fixed tree reduction.
// ---------------------------------------------------------------------------
__global__ __launch_bounds__(256) void pool_kernel(const float* __restrict__ x,
                                                   float* __restrict__ pooled) {
    int g    = blockIdx.x;
    int tid  = threadIdx.x;
    int quad = tid & (NQUAD - 1);
    int rgrp = tid >> 5;

    int start = g_start[g];
    int n     = g_start[g + 1] - start;
    float inv = 1.0f / (float)(n > 1 ? n : 1);

    const float4* __restrict__ x4 = (const float4*)x;

    float4 acc = make_float4(0.f, 0.f, 0.f, 0.f);

    // Unrolled-by-4 main loop: 4 independent outstanding 16B loads per thread.
    int r = rgrp;
    int nmain = n - 3 * RG;  // can take 4 strided rows while r < nmain
    for (; r < nmain; r += 4 * RG) {
        float4 v0 = x4[(size_t)(start + r         ) * NQUAD + quad];
        float4 v1 = x4[(size_t)(start + r + 1 * RG) * NQUAD + quad];
        float4 v2 = x4[(size_t)(start + r + 2 * RG) * NQUAD + quad];
        float4 v3 = x4[(size_t)(start + r + 3 * RG) * NQUAD + quad];
        acc.x += v0.x; acc.y += v0.y; acc.z += v0.z; acc.w += v0.w;
        acc.x += v1.x; acc.y += v1.y; acc.z += v1.z; acc.w += v1.w;
        acc.x += v2.x; acc.y += v2.y; acc.z += v2.z; acc.w += v2.w;
        acc.x += v3.x; acc.y += v3.y; acc.z += v3.z; acc.w += v3.w;
    }
    for (; r < n; r += RG) {
        float4 v = x4[(size_t)(start + r) * NQUAD + quad];
        acc.x += v.x; acc.y += v.y; acc.z += v.z; acc.w += v.w;
    }

    __shared__ float4 smem[RG * NQUAD];
    smem[rgrp * NQUAD + quad] = acc;
    __syncthreads();

    // tree reduce over row-groups: 8 -> 4 -> 2 -> 1
    #pragma unroll
    for (int half = RG / 2; half >= 1; half >>= 1) {
        if (rgrp < half) {
            float4 a = smem[rgrp * NQUAD + quad];
            float4 b = smem[(rgrp + half) * NQUAD + quad];
            a.x += b.x; a.y += b.y; a.z += b.z; a.w += b.w;
            smem[rgrp * NQUAD + quad] = a;
        }
        __syncthreads();
    }

    if (rgrp == 0) {
        float4 s = smem[quad];
        s.x *= inv; s.y *= inv; s.z *= inv; s.w *= inv;
        ((float4*)pooled)[(size_t)g * NQUAD + quad] = s;
    }
}

// ---------------------------------------------------------------------------
// K3: attention_scores[i] = 1/count(batch[i]). 4 nodes per thread (int4 read,
// float4 write). g_start table (4 KB) is L1-resident.
// ---------------------------------------------------------------------------
__global__ __launch_bounds__(256) void attn_kernel(const int* __restrict__ batch,
                                                   float* __restrict__ attn, int n) {
    int i4 = blockIdx.x * blockDim.x + threadIdx.x;   // quad index
    int nquads = n >> 2;
    if (i4 < nquads) {
        int4 b = ((const int4*)batch)[i4];
        float4 o;
        o.x = 1.0f / (float)(g_start[b.x + 1] - g_start[b.x]);
        o.y = 1.0f / (float)(g_start[b.y + 1] - g_start[b.y]);
        o.z = 1.0f / (float)(g_start[b.z + 1] - g_start[b.z]);
        o.w = 1.0f / (float)(g_start[b.w + 1] - g_start[b.w]);
        ((float4*)attn)[i4] = o;
    }
    // tail (n not divisible by 4) handled by thread 0
    if (i4 == 0) {
        for (int i = nquads << 2; i < n; i++) {
            int b = batch[i];
            attn[i] = 1.0f / (float)(g_start[b + 1] - g_start[b]);
        }
    }
}

// ---------------------------------------------------------------------------
extern "C" void kernel_launch(void* const* d_in, const int* in_sizes, int n_in,
                              void* d_out, int out_size) {
    const float* x     = (const float*)d_in[0];
    // d_in[1] = edge_index (unused by the reference)
    const int*   batch = (const int*)d_in[2];
    int n = in_sizes[2];               // number of nodes (1,000,000)

    float* pooled = (float*)d_out;                 // [NG, NFEAT]
    float* attn   = (float*)d_out + NG * NFEAT;    // [n]

    bounds_kernel<<<(n + 255) / 256, 256>>>(batch, n);
    pool_kernel<<<NG, 256>>>(x, pooled);
    int nquads = n >> 2;
    attn_kernel<<<(nquads + 255) / 256, 256>>>(batch, attn, n);
}